// round 2
// baseline (speedup 1.0000x reference)
#include <cuda_runtime.h>

#define BATCH 8
#define DIMC  384
#define NN    4096
#define HEADS 8
#define KDIM  32
#define DV    64
#define MQKV  1024
#define DH    512

// ---------------- scratch (no allocs allowed; device globals) ----------------
__device__ float g_QKV[8ull * MQKV * NN];      // q rows [0,256) k [256,512) v [512,1024)  (128 MiB)
__device__ float g_KMX[BATCH * 256];           // per key-row max
__device__ float g_KINV[BATCH * 256];          // per key-row 1/sum(exp)
__device__ float g_CTXP[BATCH * HEADS * 4 * KDIM * DV];  // partial contexts (4 N-chunks)  (2 MiB)
__device__ float g_ATT[8ull * DH * NN];        // relu(attended)  (64 MiB)

// ---------------- GEMM core: Y[b] = scale[m]*(A @ X[b]) + bias[m] ----------------
// A: [M,K] row-major; X[b]: [K,NN]; Y[b]: [M,NN]. Tile 64x64, K-tile 16, 256 thr, 4x4/thr.
__device__ __forceinline__ void gemm_core(
    const float* __restrict__ A, const float* __restrict__ Xb,
    const float* __restrict__ scale, const float* __restrict__ bias,
    float* __restrict__ Yb, int K)
{
    __shared__ float As[16][64];   // [k][m]
    __shared__ float Xs[16][64];   // [k][n]

    const int tid = threadIdx.x;
    const int tx = tid & 15, ty = tid >> 4;
    const int bm = blockIdx.y * 64, bn = blockIdx.x * 64;
    const int arow = tid >> 2, acol = (tid & 3) * 4;
    const int xrow = tid >> 4, xcol = (tid & 15) * 4;

    float acc[4][4] = {};

    for (int k0 = 0; k0 < K; k0 += 16) {
        float4 a4 = *(const float4*)(A + (size_t)(bm + arow) * K + k0 + acol);
        As[acol + 0][arow] = a4.x;
        As[acol + 1][arow] = a4.y;
        As[acol + 2][arow] = a4.z;
        As[acol + 3][arow] = a4.w;
        *(float4*)&Xs[xrow][xcol] = *(const float4*)(Xb + (size_t)(k0 + xrow) * NN + bn + xcol);
        __syncthreads();
        #pragma unroll
        for (int kk = 0; kk < 16; kk++) {
            float4 av = *(float4*)&As[kk][ty * 4];
            float4 xv = *(float4*)&Xs[kk][tx * 4];
            acc[0][0] += av.x * xv.x; acc[0][1] += av.x * xv.y; acc[0][2] += av.x * xv.z; acc[0][3] += av.x * xv.w;
            acc[1][0] += av.y * xv.x; acc[1][1] += av.y * xv.y; acc[1][2] += av.y * xv.z; acc[1][3] += av.y * xv.w;
            acc[2][0] += av.z * xv.x; acc[2][1] += av.z * xv.y; acc[2][2] += av.z * xv.z; acc[2][3] += av.z * xv.w;
            acc[3][0] += av.w * xv.x; acc[3][1] += av.w * xv.y; acc[3][2] += av.w * xv.z; acc[3][3] += av.w * xv.w;
        }
        __syncthreads();
    }

    #pragma unroll
    for (int i = 0; i < 4; i++) {
        int m = bm + ty * 4 + i;
        float s = scale[m], bb = bias[m];
        float4 o;
        o.x = acc[i][0] * s + bb;
        o.y = acc[i][1] * s + bb;
        o.z = acc[i][2] * s + bb;
        o.w = acc[i][3] * s + bb;
        *(float4*)(Yb + (size_t)m * NN + bn + tx * 4) = o;
    }
}

// QKV projection: writes into g_QKV at row offset mOff (no host symbol lookup needed)
__global__ __launch_bounds__(256) void gemm_qkv(
    const float* __restrict__ A, const float* __restrict__ x,
    const float* __restrict__ scale, const float* __restrict__ bias,
    int mOff, int K)
{
    const int b = blockIdx.z;
    const float* Xb = x + (size_t)b * K * NN;
    float* Yb = g_QKV + ((size_t)b * MQKV + mOff) * NN;
    gemm_core(A, Xb, scale, bias, Yb, K);
}

// Output projection: reads g_ATT, writes harness out
__global__ __launch_bounds__(256) void gemm_proj(
    const float* __restrict__ A,
    const float* __restrict__ scale, const float* __restrict__ bias,
    float* __restrict__ Y, int K)
{
    const int b = blockIdx.z;
    const float* Xb = g_ATT + (size_t)b * K * NN;
    float* Yb = Y + (size_t)b * DIMC * NN;
    gemm_core(A, Xb, scale, bias, Yb, K);
}

// ---------------- key stats: per key-row max and 1/sum(exp) over N ----------------
__global__ __launch_bounds__(256) void key_stats()
{
    const int row = blockIdx.x;            // 0..2047
    const int b = row >> 8, c = row & 255;
    const float* p = g_QKV + (size_t)b * MQKV * NN + (size_t)(256 + c) * NN;
    const int tid = threadIdx.x;

    float v[16];
    float mx = -3.4e38f;
    #pragma unroll
    for (int i = 0; i < 16; i++) { v[i] = p[i * 256 + tid]; mx = fmaxf(mx, v[i]); }

    __shared__ float red[256];
    red[tid] = mx; __syncthreads();
    for (int s = 128; s > 0; s >>= 1) { if (tid < s) red[tid] = fmaxf(red[tid], red[tid + s]); __syncthreads(); }
    mx = red[0]; __syncthreads();

    float sum = 0.f;
    #pragma unroll
    for (int i = 0; i < 16; i++) sum += __expf(v[i] - mx);
    red[tid] = sum; __syncthreads();
    for (int s = 128; s > 0; s >>= 1) { if (tid < s) red[tid] += red[tid + s]; __syncthreads(); }

    if (tid == 0) { g_KMX[row] = mx; g_KINV[row] = 1.f / red[0]; }
}

// ---------------- context partials: ctxp[bh,chunk,kd,d] = sum_{n in chunk} softmax(k)*v ----------
// grid 256 = (bh=64) x (chunk=4). exp applied on the fly; inv applied in epilogue. No atomics.
__global__ __launch_bounds__(256) void context_kernel()
{
    const int bh = blockIdx.x >> 2;
    const int chunk = blockIdx.x & 3;
    const int b = bh >> 3, h = bh & 7;
    const float* Kp = g_QKV + (size_t)b * MQKV * NN + (size_t)(256 + h * KDIM) * NN;
    const float* Vp = g_QKV + (size_t)b * MQKV * NN + (size_t)(512 + h * DV) * NN;

    __shared__ float ks[KDIM][65];
    __shared__ float vs[DV][65];
    __shared__ float smx[KDIM], sinv[KDIM];

    const int tid = threadIdx.x;
    if (tid < KDIM) {
        int row = b * 256 + h * KDIM + tid;
        smx[tid] = g_KMX[row];
        sinv[tid] = g_KINV[row];
    }
    __syncthreads();

    const int d = tid & 63, kb = tid >> 6;   // kd = kb + 4*j
    float acc[8] = {};

    const int n0base = chunk * 1024;
    for (int n0 = n0base; n0 < n0base + 1024; n0 += 64) {
        #pragma unroll
        for (int i = 0; i < 8; i++) {
            int idx = tid + i * 256;
            int r = idx >> 6, cc = idx & 63;
            ks[r][cc] = __expf(Kp[(size_t)r * NN + n0 + cc] - smx[r]);
        }
        #pragma unroll
        for (int i = 0; i < 16; i++) {
            int idx = tid + i * 256;
            vs[idx >> 6][idx & 63] = Vp[(size_t)(idx >> 6) * NN + n0 + (idx & 63)];
        }
        __syncthreads();
        #pragma unroll 8
        for (int nn = 0; nn < 64; nn++) {
            float vv = vs[d][nn];
            #pragma unroll
            for (int j = 0; j < 8; j++) acc[j] += ks[kb + 4 * j][nn] * vv;
        }
        __syncthreads();
    }
    float* dst = g_CTXP + ((size_t)bh * 4 + chunk) * (KDIM * DV);
    #pragma unroll
    for (int j = 0; j < 8; j++)
        dst[(kb + 4 * j) * DV + d] = acc[j] * sinv[kb + 4 * j];
}

// ---------------- attended = relu(ctx^T @ softmax_kd(q)), query softmax fused ----------------
// grid 512: (bh=64) x 8 tiles of 512 columns; each thread handles 2 columns.
__global__ __launch_bounds__(256) void attended_kernel()
{
    const int bh = blockIdx.x >> 3;
    const int nt = (blockIdx.x & 7) * 512;
    const int b = bh >> 3, h = bh & 7;

    __shared__ float C[KDIM * DV];
    const int tid = threadIdx.x;
    const float* cp = g_CTXP + (size_t)bh * 4 * (KDIM * DV);
    #pragma unroll
    for (int i = 0; i < 8; i++) {
        int idx = tid + i * 256;
        C[idx] = cp[idx] + cp[idx + 2048] + cp[idx + 4096] + cp[idx + 6144];
    }
    __syncthreads();

    const float* Qp = g_QKV + (size_t)b * MQKV * NN + (size_t)(h * KDIM) * NN;
    float* Ap = g_ATT + (size_t)b * DH * NN + (size_t)(h * DV) * NN;

    const int n1 = nt + tid, n2 = nt + 256 + tid;
    float q1[KDIM], q2[KDIM];
    float m1 = -3.4e38f, m2 = -3.4e38f;
    #pragma unroll
    for (int kd = 0; kd < KDIM; kd++) {
        q1[kd] = Qp[(size_t)kd * NN + n1];
        q2[kd] = Qp[(size_t)kd * NN + n2];
        m1 = fmaxf(m1, q1[kd]);
        m2 = fmaxf(m2, q2[kd]);
    }
    float s1 = 0.f, s2 = 0.f;
    #pragma unroll
    for (int kd = 0; kd < KDIM; kd++) {
        q1[kd] = __expf(q1[kd] - m1); s1 += q1[kd];
        q2[kd] = __expf(q2[kd] - m2); s2 += q2[kd];
    }
    float i1 = 1.f / s1, i2 = 1.f / s2;
    #pragma unroll
    for (int kd = 0; kd < KDIM; kd++) { q1[kd] *= i1; q2[kd] *= i2; }

    for (int dd = 0; dd < DV; dd++) {
        float a1 = 0.f, a2 = 0.f;
        #pragma unroll
        for (int kd = 0; kd < KDIM; kd++) {
            float cc = C[kd * DV + dd];
            a1 += cc * q1[kd];
            a2 += cc * q2[kd];
        }
        Ap[(size_t)dd * NN + n1] = fmaxf(a1, 0.f);
        Ap[(size_t)dd * NN + n2] = fmaxf(a2, 0.f);
    }
}

// ---------------- launch: kernel launches ONLY ----------------
extern "C" void kernel_launch(void* const* d_in, const int* /*in_sizes*/, int /*n_in*/,
                              void* d_out, int /*out_size*/)
{
    const float* x  = (const float*)d_in[0];
    const float* Wq = (const float*)d_in[1];
    const float* sq = (const float*)d_in[2];
    const float* bq = (const float*)d_in[3];
    const float* Wk = (const float*)d_in[4];
    const float* sk = (const float*)d_in[5];
    const float* bk = (const float*)d_in[6];
    const float* Wv = (const float*)d_in[7];
    const float* sv = (const float*)d_in[8];
    const float* bv = (const float*)d_in[9];
    const float* Wp = (const float*)d_in[10];
    const float* sp = (const float*)d_in[11];
    const float* bp = (const float*)d_in[12];
    float* out = (float*)d_out;

    // 1) Q/K/V projections + BN affine into g_QKV
    gemm_qkv<<<dim3(64, 4, BATCH), 256>>>(Wq, x, sq, bq, 0,   DIMC);
    gemm_qkv<<<dim3(64, 4, BATCH), 256>>>(Wk, x, sk, bk, 256, DIMC);
    gemm_qkv<<<dim3(64, 8, BATCH), 256>>>(Wv, x, sv, bv, 512, DIMC);
    // 2) key softmax stats (max, 1/sum)
    key_stats<<<2048, 256>>>();
    // 3) context partials (softmax applied on the fly, no atomics)
    context_kernel<<<256, 256>>>();
    // 4) attended = relu(ctx^T @ softmax(q)), query softmax fused
    attended_kernel<<<512, 256>>>();
    // 5) output projection + BN affine
    gemm_proj<<<dim3(64, 6, BATCH), 256>>>(Wp, sp, bp, out, DH);
}

// round 4
// speedup vs baseline: 1.9845x; 1.9845x over previous
#include <cuda_runtime.h>
#include <cuda_bf16.h>
#include <mma.h>
#include <cstdint>

using namespace nvcuda;

#define BATCH 8
#define DIMC  384
#define NN    4096
#define HEADS 8
#define KDIM  32
#define DV    64
#define MQKV  1024
#define DH    512
#define KQP   416        // 384 + bias col + pad, mult of 32
#define KPP   544        // 512 + bias col + pad, mult of 32

// ---------------- device scratch ----------------
__device__ __nv_bfloat16 g_WQKVh[MQKV * KQP];   // pre-scaled weights + bias col (hi)
__device__ __nv_bfloat16 g_WQKVl[MQKV * KQP];
__device__ __nv_bfloat16 g_WPh[DIMC * KPP];
__device__ __nv_bfloat16 g_WPl[DIMC * KPP];
__device__ __nv_bfloat16 g_XTh[8ull * NN * KQP];    // x^T split + ones col
__device__ __nv_bfloat16 g_XTl[8ull * NN * KQP];
__device__ float g_QKV[8ull * MQKV * NN];           // q[0:256) k[256:512) v[512:1024)
__device__ float g_KMX[BATCH * 256];
__device__ float g_KINV[BATCH * 256];
__device__ float g_CTXP[BATCH * HEADS * 4 * KDIM * DV];
__device__ __nv_bfloat16 g_ATTh[8ull * NN * KPP];   // relu(attended)^T split + ones col
__device__ __nv_bfloat16 g_ATTl[8ull * NN * KPP];

__device__ __forceinline__ uint32_t smem_u32(const void* p) {
    uint32_t a;
    asm("{ .reg .u64 t; cvta.to.shared.u64 t, %1; cvt.u32.u64 %0, t; }" : "=r"(a) : "l"(p));
    return a;
}
__device__ __forceinline__ void cp_async16(uint32_t dst, const void* src) {
    asm volatile("cp.async.cg.shared.global [%0], [%1], 16;" :: "r"(dst), "l"(src));
}
__device__ __forceinline__ void cp_commit() { asm volatile("cp.async.commit_group;"); }
__device__ __forceinline__ void cp_wait1()  { asm volatile("cp.async.wait_group 1;"); }
__device__ __forceinline__ void cp_wait0()  { asm volatile("cp.async.wait_group 0;"); }

__device__ __forceinline__ void split2(float x, __nv_bfloat16& h, __nv_bfloat16& l) {
    h = __float2bfloat16(x);
    l = __float2bfloat16(x - __bfloat162float(h));
}

// ---------------- prep: pre-scaled weight split, bias column, padding ----------------
__global__ __launch_bounds__(256) void prep_w(
    const float* __restrict__ Wq, const float* __restrict__ sq, const float* __restrict__ bq,
    const float* __restrict__ Wk, const float* __restrict__ sk, const float* __restrict__ bk,
    const float* __restrict__ Wv, const float* __restrict__ sv, const float* __restrict__ bv,
    const float* __restrict__ Wp, const float* __restrict__ sp, const float* __restrict__ bp)
{
    int i = blockIdx.x * 256 + threadIdx.x;
    if (i < MQKV * KQP) {
        int m = i / KQP, kk = i - m * KQP;
        float w;
        if (kk < DIMC) {
            if (m < 256)      w = Wq[m * DIMC + kk] * sq[m];
            else if (m < 512) w = Wk[(m - 256) * DIMC + kk] * sk[m - 256];
            else              w = Wv[(m - 512) * DIMC + kk] * sv[m - 512];
        } else if (kk == DIMC) {
            w = (m < 256) ? bq[m] : (m < 512) ? bk[m - 256] : bv[m - 512];
        } else w = 0.f;
        split2(w, g_WQKVh[i], g_WQKVl[i]);
    } else {
        int j = i - MQKV * KQP;       // < DIMC*KPP by grid sizing
        int m = j / KPP, kk = j - m * KPP;
        float w;
        if (kk < DH)       w = Wp[m * DH + kk] * sp[m];
        else if (kk == DH) w = bp[m];
        else               w = 0.f;
        split2(w, g_WPh[j], g_WPl[j]);
    }
}

// ---------------- x transpose + split: x[b][c][n] -> XT[b][n][k], k stride KQP -----------
__global__ __launch_bounds__(256) void conv_x(const float* __restrict__ x)
{
    const int b = blockIdx.z, n0 = blockIdx.x * 64;
    const int tid = threadIdx.x;

    if (blockIdx.y == 12) {   // tail cols 384..415: ones col + zeros
        const int nl = tid >> 2, cg = (tid & 3) * 8;
        size_t dst = ((size_t)b * NN + n0 + nl) * KQP + DIMC + cg;
        uint4 z = {0, 0, 0, 0};
        uint4 vh = z;
        if (cg == 0) ((__nv_bfloat16*)&vh)[0] = __float2bfloat16(1.0f);
        *(uint4*)(g_XTh + dst) = vh;
        *(uint4*)(g_XTl + dst) = z;
        return;
    }

    __shared__ float t[32][65];
    const int c0 = blockIdx.y * 32;
    const int col = tid & 63, r0 = tid >> 6;
    #pragma unroll
    for (int i = 0; i < 8; i++) {
        int row = r0 + i * 4;
        t[row][col] = x[((size_t)b * DIMC + c0 + row) * NN + n0 + col];
    }
    __syncthreads();
    const int nl = tid >> 2, cc = (tid & 3) * 8;
    size_t dst = ((size_t)b * NN + n0 + nl) * KQP + c0 + cc;
    uint4 vh, vl;
    __nv_bfloat162* ph = (__nv_bfloat162*)&vh;
    __nv_bfloat162* pl = (__nv_bfloat162*)&vl;
    #pragma unroll
    for (int j = 0; j < 4; j++) {
        __nv_bfloat16 h0, l0, h1, l1;
        split2(t[cc + 2 * j][nl], h0, l0);
        split2(t[cc + 2 * j + 1][nl], h1, l1);
        ph[j].x = h0; ph[j].y = h1;
        pl[j].x = l0; pl[j].y = l1;
    }
    *(uint4*)(g_XTh + dst) = vh;
    *(uint4*)(g_XTl + dst) = vl;
}

// ---------------- wmma split-bf16 GEMM, BN fully folded, cp.async double buffer ---------
// Y[m,n] = sum_k A[m,k]*B[n,k]. CTA tile 128x128, k-chunk 32, 8 warps (32x64 each).
#define LDT 40                      // smem tile ld (elements)
#define TILE_B (128 * LDT * 2)      // 10240 bytes per tile
#define STAGE_B (4 * TILE_B)        // Ah, Al, Bh, Bl
#define SMEM_WMMA (2 * STAGE_B)     // 81920

__global__ __launch_bounds__(256) void gemm_wmma(int mode, float* __restrict__ outp)
{
    extern __shared__ char smem[];
    const int tid = threadIdx.x;
    const int b = blockIdx.z;
    const int bn = blockIdx.x * 128, bm = blockIdx.y * 128;

    const __nv_bfloat16 *pA[2], *pB[2];
    float* Y;
    int Kp;
    if (mode == 0) {
        Kp = KQP;
        pA[0] = g_WQKVh + (size_t)bm * Kp;
        pA[1] = g_WQKVl + (size_t)bm * Kp;
        pB[0] = g_XTh + ((size_t)b * NN + bn) * Kp;
        pB[1] = g_XTl + ((size_t)b * NN + bn) * Kp;
        Y = g_QKV + (size_t)b * MQKV * NN;
    } else {
        Kp = KPP;
        pA[0] = g_WPh + (size_t)bm * Kp;
        pA[1] = g_WPl + (size_t)bm * Kp;
        pB[0] = g_ATTh + ((size_t)b * NN + bn) * Kp;
        pB[1] = g_ATTl + ((size_t)b * NN + bn) * Kp;
        Y = outp + (size_t)b * DIMC * NN;
    }

    const uint32_t smem_base = smem_u32(smem);
    const int erow = tid >> 2, ecg = (tid & 3) * 8;   // loader: 2 uint4/thread/tile

    auto issue_stage = [&](int st, int k0) {
        uint32_t sb = smem_base + st * STAGE_B;
        #pragma unroll
        for (int tile = 0; tile < 4; tile++) {
            const __nv_bfloat16* src = (tile < 2) ? pA[tile] : pB[tile - 2];
            #pragma unroll
            for (int r = 0; r < 2; r++) {
                int row = erow + r * 64;
                cp_async16(sb + tile * TILE_B + (row * LDT + ecg) * 2,
                           src + (size_t)row * Kp + k0 + ecg);
            }
        }
        cp_commit();
    };

    const int wid = tid >> 5;
    const int wm = wid & 3, wn = wid >> 2;     // warp tile: rows wm*32, cols wn*64

    wmma::fragment<wmma::accumulator, 16, 16, 16, float> acc[2][4];
    #pragma unroll
    for (int i = 0; i < 2; i++)
        #pragma unroll
        for (int j = 0; j < 4; j++) wmma::fill_fragment(acc[i][j], 0.f);

    const int nkt = Kp >> 5;
    issue_stage(0, 0);

    for (int kt = 0; kt < nkt; kt++) {
        if (kt + 1 < nkt) { issue_stage((kt + 1) & 1, (kt + 1) << 5); cp_wait1(); }
        else cp_wait0();
        __syncthreads();

        const char* sb = smem + (kt & 1) * STAGE_B;
        const __nv_bfloat16* Ah = (const __nv_bfloat16*)(sb);
        const __nv_bfloat16* Al = (const __nv_bfloat16*)(sb + TILE_B);
        const __nv_bfloat16* Bh = (const __nv_bfloat16*)(sb + 2 * TILE_B);
        const __nv_bfloat16* Bl = (const __nv_bfloat16*)(sb + 3 * TILE_B);

        #pragma unroll
        for (int ks = 0; ks < 2; ks++) {
            wmma::fragment<wmma::matrix_a, 16, 16, 16, __nv_bfloat16, wmma::row_major> ah[2], al[2];
            wmma::fragment<wmma::matrix_b, 16, 16, 16, __nv_bfloat16, wmma::col_major> bh[4], bl[4];
            #pragma unroll
            for (int i = 0; i < 2; i++) {
                wmma::load_matrix_sync(ah[i], Ah + (wm * 32 + i * 16) * LDT + ks * 16, LDT);
                wmma::load_matrix_sync(al[i], Al + (wm * 32 + i * 16) * LDT + ks * 16, LDT);
            }
            #pragma unroll
            for (int j = 0; j < 4; j++) {
                wmma::load_matrix_sync(bh[j], Bh + (wn * 64 + j * 16) * LDT + ks * 16, LDT);
                wmma::load_matrix_sync(bl[j], Bl + (wn * 64 + j * 16) * LDT + ks * 16, LDT);
            }
            #pragma unroll
            for (int i = 0; i < 2; i++)
                #pragma unroll
                for (int j = 0; j < 4; j++) {
                    wmma::mma_sync(acc[i][j], ah[i], bh[j], acc[i][j]);
                    wmma::mma_sync(acc[i][j], ah[i], bl[j], acc[i][j]);
                    wmma::mma_sync(acc[i][j], al[i], bh[j], acc[i][j]);
                }
        }
        __syncthreads();
    }

    #pragma unroll
    for (int i = 0; i < 2; i++)
        #pragma unroll
        for (int j = 0; j < 4; j++)
            wmma::store_matrix_sync(Y + (size_t)(bm + wm * 32 + i * 16) * NN + bn + wn * 64 + j * 16,
                                    acc[i][j], NN, wmma::mem_row_major);
}

// ---------------- key softmax stats ----------------
__global__ __launch_bounds__(256) void key_stats()
{
    const int row = blockIdx.x;            // 0..2047
    const int b = row >> 8, c = row & 255;
    const float* p = g_QKV + (size_t)b * MQKV * NN + (size_t)(256 + c) * NN;
    const int tid = threadIdx.x;

    float v[16];
    float mx = -3.4e38f;
    #pragma unroll
    for (int i = 0; i < 16; i++) { v[i] = p[i * 256 + tid]; mx = fmaxf(mx, v[i]); }

    __shared__ float red[256];
    red[tid] = mx; __syncthreads();
    for (int s = 128; s > 0; s >>= 1) { if (tid < s) red[tid] = fmaxf(red[tid], red[tid + s]); __syncthreads(); }
    mx = red[0]; __syncthreads();

    float sum = 0.f;
    #pragma unroll
    for (int i = 0; i < 16; i++) sum += __expf(v[i] - mx);
    red[tid] = sum; __syncthreads();
    for (int s = 128; s > 0; s >>= 1) { if (tid < s) red[tid] += red[tid + s]; __syncthreads(); }

    if (tid == 0) { g_KMX[row] = mx; g_KINV[row] = 1.f / red[0]; }
}

// ---------------- context partials ----------------
__global__ __launch_bounds__(256) void context_kernel()
{
    const int bh = blockIdx.x >> 2;
    const int chunk = blockIdx.x & 3;
    const int b = bh >> 3, h = bh & 7;
    const float* Kp = g_QKV + (size_t)b * MQKV * NN + (size_t)(256 + h * KDIM) * NN;
    const float* Vp = g_QKV + (size_t)b * MQKV * NN + (size_t)(512 + h * DV) * NN;

    __shared__ float ks[KDIM][65];
    __shared__ float vs[DV][65];
    __shared__ float smx[KDIM], sinv[KDIM];

    const int tid = threadIdx.x;
    if (tid < KDIM) {
        int row = b * 256 + h * KDIM + tid;
        smx[tid] = g_KMX[row];
        sinv[tid] = g_KINV[row];
    }
    __syncthreads();

    const int d = tid & 63, kb = tid >> 6;
    float acc[8] = {};

    const int n0base = chunk * 1024;
    for (int n0 = n0base; n0 < n0base + 1024; n0 += 64) {
        #pragma unroll
        for (int i = 0; i < 8; i++) {
            int idx = tid + i * 256;
            int r = idx >> 6, cc = idx & 63;
            ks[r][cc] = __expf(Kp[(size_t)r * NN + n0 + cc] - smx[r]);
        }
        #pragma unroll
        for (int i = 0; i < 16; i++) {
            int idx = tid + i * 256;
            vs[idx >> 6][idx & 63] = Vp[(size_t)(idx >> 6) * NN + n0 + (idx & 63)];
        }
        __syncthreads();
        #pragma unroll 8
        for (int nn = 0; nn < 64; nn++) {
            float vv = vs[d][nn];
            #pragma unroll
            for (int j = 0; j < 8; j++) acc[j] += ks[kb + 4 * j][nn] * vv;
        }
        __syncthreads();
    }
    float* dst = g_CTXP + ((size_t)bh * 4 + chunk) * (KDIM * DV);
    #pragma unroll
    for (int j = 0; j < 8; j++)
        dst[(kb + 4 * j) * DV + d] = acc[j] * sinv[kb + 4 * j];
}

// ---------------- attended: relu(ctx^T @ softmax(q)) -> transposed bf16 split ------------
__global__ __launch_bounds__(256) void attended_kernel()
{
    const int bh = blockIdx.x >> 4;
    const int nt = (blockIdx.x & 15) * 256;
    const int b = bh >> 3, h = bh & 7;

    __shared__ float C[KDIM * DV];
    const int tid = threadIdx.x;
    const float* cp = g_CTXP + (size_t)bh * 4 * (KDIM * DV);
    #pragma unroll
    for (int i = 0; i < 8; i++) {
        int idx = tid + i * 256;
        C[idx] = cp[idx] + cp[idx + 2048] + cp[idx + 4096] + cp[idx + 6144];
    }
    __syncthreads();

    const int n = nt + tid;
    const float* Qp = g_QKV + (size_t)b * MQKV * NN + (size_t)(h * KDIM) * NN + n;

    float q[KDIM];
    float mx = -3.4e38f;
    #pragma unroll
    for (int kd = 0; kd < KDIM; kd++) { q[kd] = Qp[(size_t)kd * NN]; mx = fmaxf(mx, q[kd]); }
    float sum = 0.f;
    #pragma unroll
    for (int kd = 0; kd < KDIM; kd++) { q[kd] = __expf(q[kd] - mx); sum += q[kd]; }
    const float inv = 1.f / sum;
    #pragma unroll
    for (int kd = 0; kd < KDIM; kd++) q[kd] *= inv;

    __nv_bfloat16* dh = g_ATTh + ((size_t)b * NN + n) * KPP + h * DV;
    __nv_bfloat16* dl = g_ATTl + ((size_t)b * NN + n) * KPP + h * DV;

    #pragma unroll
    for (int g = 0; g < 8; g++) {
        float a[8];
        #pragma unroll
        for (int j = 0; j < 8; j++) {
            const int dd = g * 8 + j;
            float s = 0.f;
            #pragma unroll
            for (int kd = 0; kd < KDIM; kd++) s += C[kd * DV + dd] * q[kd];
            a[j] = fmaxf(s, 0.f);
        }
        uint4 vh, vl;
        __nv_bfloat162* ph = (__nv_bfloat162*)&vh;
        __nv_bfloat162* pl = (__nv_bfloat162*)&vl;
        #pragma unroll
        for (int j = 0; j < 4; j++) {
            __nv_bfloat16 h0, l0, h1, l1;
            split2(a[2 * j], h0, l0);
            split2(a[2 * j + 1], h1, l1);
            ph[j].x = h0; ph[j].y = h1;
            pl[j].x = l0; pl[j].y = l1;
        }
        *(uint4*)(dh + g * 8) = vh;
        *(uint4*)(dl + g * 8) = vl;
    }

    if (h == 0) {   // tail cols 512..543: ones col + zeros
        uint4 z = {0, 0, 0, 0};
        __nv_bfloat16* th = g_ATTh + ((size_t)b * NN + n) * KPP + DH;
        __nv_bfloat16* tl = g_ATTl + ((size_t)b * NN + n) * KPP + DH;
        uint4 v0 = z;
        ((__nv_bfloat16*)&v0)[0] = __float2bfloat16(1.0f);
        *(uint4*)(th) = v0;
        *(uint4*)(th + 8) = z; *(uint4*)(th + 16) = z; *(uint4*)(th + 24) = z;
        *(uint4*)(tl) = z; *(uint4*)(tl + 8) = z; *(uint4*)(tl + 16) = z; *(uint4*)(tl + 24) = z;
    }
}

// ---------------- launch ----------------
extern "C" void kernel_launch(void* const* d_in, const int* /*in_sizes*/, int /*n_in*/,
                              void* d_out, int /*out_size*/)
{
    const float* x  = (const float*)d_in[0];
    const float* Wq = (const float*)d_in[1];
    const float* sq = (const float*)d_in[2];
    const float* bq = (const float*)d_in[3];
    const float* Wk = (const float*)d_in[4];
    const float* sk = (const float*)d_in[5];
    const float* bk = (const float*)d_in[6];
    const float* Wv = (const float*)d_in[7];
    const float* sv = (const float*)d_in[8];
    const float* bv = (const float*)d_in[9];
    const float* Wp = (const float*)d_in[10];
    const float* sp = (const float*)d_in[11];
    const float* bp = (const float*)d_in[12];
    float* out = (float*)d_out;

    static int smem_set = 0;
    if (!smem_set) {
        cudaFuncSetAttribute(gemm_wmma, cudaFuncAttributeMaxDynamicSharedMemorySize, SMEM_WMMA);
        smem_set = 1;
    }

    // 1) pre-scaled weight split + bias columns   ((1024*416 + 384*544)/256 = 2480)
    prep_w<<<2480, 256>>>(Wq, sq, bq, Wk, sk, bk, Wv, sv, bv, Wp, sp, bp);
    // 2) x transpose + bf16 split + ones column
    conv_x<<<dim3(64, 13, BATCH), 256>>>(x);
    // 3) QKV projection (tensor cores, BN folded)
    gemm_wmma<<<dim3(32, 8, BATCH), 256, SMEM_WMMA>>>(0, nullptr);
    // 4) key softmax stats
    key_stats<<<2048, 256>>>();
    // 5) context partials
    context_kernel<<<256, 256>>>();
    // 6) attended (+query softmax, ReLU, transpose, split, ones column)
    attended_kernel<<<1024, 256>>>();
    // 7) output projection (tensor cores, BN folded)
    gemm_wmma<<<dim3(32, 3, BATCH), 256, SMEM_WMMA>>>(1, out);
}